// round 12
// baseline (speedup 1.0000x reference)
#include <cuda_runtime.h>
#include <cstdint>

// Problem constants
#define NPTS 200000
#define NCLS 20
#define NPROP 256
#define NPAIR 400000
#define THRESH 100

// Derived
#define WPP (NPTS / 32)                 // 6250 words per proposal
#define WORDS ((size_t)NPROP * WPP)     // 1,600,000 words

// Output layout (float32, concatenated in return order)
#define OFF_SCORES  ((size_t)0)
#define OFF_MASKS   ((size_t)256)
#define OFF_CLASSES ((size_t)(256 + (size_t)NPROP * NPTS))
#define OFF_BIAS    (OFF_CLASSES + 256)
#define OFF_PROBS   (OFF_BIAS + (size_t)NPTS * 3)

#define PAD 32   // 128B stride between per-proposal counters

// Scratch (device globals: allocation-free)
__device__ unsigned int g_bits[WORDS];          // 6.4 MB dedupe bitmask
__device__ unsigned char g_first[NPAIR];        // per-pair first-setter verdict
__device__ int   g_rep_p[NPROP * PAD];
__device__ int   g_count_p[NPROP * PAD];
__device__ float g_score_p[NPROP * PAD];
__device__ int   g_segpred[NPTS];
__device__ int   g_ticket;                      // gather completion ticket

// Fast exp on FMA pipe (no MUFU). rel err ~2e-6.
__device__ __forceinline__ float fexp(float x) {
    const float MAGIC = 12582912.0f;           // 1.5 * 2^23
    float t = fmaf(x, 1.4426950408889634f, MAGIC);
    int   n = __float_as_int(t) - 0x4B400000;
    float f = fmaf(x, 1.4426950408889634f, -(t - MAGIC));
    float p = 1.3333558146e-3f;
    p = fmaf(p, f, 9.6181291076e-3f);
    p = fmaf(p, f, 5.5504108664e-2f);
    p = fmaf(p, f, 2.4022650696e-1f);
    p = fmaf(p, f, 6.9314718056e-1f);
    p = fmaf(p, f, 1.0f);
    return __int_as_float(__float_as_int(p) + (n << 23));
}

// --- sH: fused pair pass: atomicOr + verdict + smem segmin + smem count.
// Also resets the gather ticket (ordered before gather via event).
__global__ void __launch_bounds__(1024, 2)
k_pairs(const int* __restrict__ pid, const int* __restrict__ nid) {
    __shared__ int s_min[NPROP];
    __shared__ int s_cnt[NPROP];
    int tid = threadIdx.x;
    if (tid < NPROP) { s_min[tid] = 0x7FFFFFFF; s_cnt[tid] = 0; }
    if (blockIdx.x == 0 && tid == 0) g_ticket = 0;
    __syncthreads();

    int stride = gridDim.x * blockDim.x;
    for (int m = blockIdx.x * blockDim.x + tid; m < NPAIR; m += stride) {
        int p = pid[m];
        int n = nid[m];
        atomicMin(&s_min[p], n);
        size_t bit = (size_t)p * NPTS + n;
        unsigned int msk = 1u << (bit & 31u);
        unsigned int old = atomicOr(&g_bits[bit >> 5], msk);
        unsigned char fst = (old & msk) ? 0 : 1;
        g_first[m] = fst;
        if (fst) atomicAdd(&s_cnt[p], 1);
    }
    __syncthreads();
    if (tid < NPROP) {
        if (s_min[tid] != 0x7FFFFFFF) atomicMin(&g_rep_p[tid * PAD], s_min[tid]);
        if (s_cnt[tid]) atomicAdd(&g_count_p[tid * PAD], s_cnt[tid]);
    }
}

// --- sH: mask expansion (warp-coalesced 512B stores) ---
__global__ void k_masks(float* __restrict__ out_masks) {
    int tid = threadIdx.x;
    int t = blockIdx.x * blockDim.x + tid;   // word index (exact grid)
    int lane = tid & 31;
    int p = t / WPP;
    unsigned int w = g_bits[t];
    if (g_count_p[p * PAD] <= THRESH) w = 0u;

    size_t warp_word0 = (size_t)(t - lane);
    float4* dst = (float4*)out_masks + warp_word0 * 8;   // 8 float4 per word
    int nib = (lane & 7) * 4;
#pragma unroll
    for (int i = 0; i < 8; i++) {
        unsigned int src = __shfl_sync(0xFFFFFFFFu, w, i * 4 + (lane >> 3));
        float4 f;
        f.x = (float)((src >> (nib + 0)) & 1u);
        f.y = (float)((src >> (nib + 1)) & 1u);
        f.z = (float)((src >> (nib + 2)) & 1u);
        f.w = (float)((src >> (nib + 3)) & 1u);
        dst[(size_t)i * 32 + lane] = f;
    }
}

// --- sB: staged softmax + argmax + fused bias passthrough ---
__global__ void k_softmax(const float* __restrict__ logit,
                          float* __restrict__ probs_out,
                          const float* __restrict__ bias,
                          float* __restrict__ bias_out) {
    __shared__ float s[256 * 21];   // 21 KB
    int tid  = threadIdx.x;
    int base = blockIdx.x * 256;

    // fused bias copy: one float4 per thread across the grid (150000 total)
    {
        int bi = blockIdx.x * 256 + tid;
        if (bi < NPTS * 3 / 4) ((float4*)bias_out)[bi] = ((const float4*)bias)[bi];
    }

    int count = NPTS - base;
    if (count > 256) count = 256;
    int tot = count * NCLS;

    const float* src = logit + (size_t)base * NCLS;
    for (int i = tid; i < tot; i += 256) {
        int row = i / NCLS, col = i - row * NCLS;
        s[row * 21 + col] = src[i];
    }
    __syncthreads();

    if (tid < count) {
        float* row = s + tid * 21;
        float v[NCLS];
#pragma unroll
        for (int i = 0; i < NCLS; i++) v[i] = row[i];
        float m = v[0]; int am = 0;
#pragma unroll
        for (int i = 1; i < NCLS; i++) if (v[i] > m) { m = v[i]; am = i; }
        float e[NCLS]; float sum = 0.0f;
#pragma unroll
        for (int i = 0; i < NCLS; i++) { e[i] = fexp(v[i] - m); sum += e[i]; }
        float inv = 1.0f / sum;
#pragma unroll
        for (int i = 0; i < NCLS; i++) row[i] = e[i] * inv;
        g_segpred[base + tid] = am;
    }
    __syncthreads();

    float* dst = probs_out + (size_t)base * NCLS;
    for (int i = tid; i < tot; i += 256) {
        int row = i / NCLS, col = i - row * NCLS;
        dst[i] = s[row * 21 + col];
    }
}

// --- sB: score gather (2 pairs/thread, batched loads) + ticketed finalize ---
#define GB 512
#define GPT 2
#define GGRID ((NPAIR + GB * GPT - 1) / (GB * GPT))   // 391
__global__ void __launch_bounds__(GB)
k_gather(const int* __restrict__ pid, const int* __restrict__ nid,
         const float* __restrict__ probs,
         float* __restrict__ out_scores, float* __restrict__ out_classes) {
    __shared__ int   s_inst[NPROP];
    __shared__ float s_scr[NPROP];
    int tid = threadIdx.x;
    if (tid < NPROP) {
        int r = g_rep_p[tid * PAD];
        if (r > NPTS - 1) r = NPTS - 1;
        s_inst[tid] = g_segpred[r];
        s_scr[tid] = 0.0f;
    }
    __syncthreads();

    // batched loads: both pairs' data in flight before use
    int m0 = blockIdx.x * (GB * GPT) + tid;
    int p0 = 0, n0 = 0, p1 = 0, n1 = 0;
    unsigned char f0 = 0, f1 = 0;
    int m1 = m0 + GB;
    if (m0 < NPAIR) { p0 = pid[m0]; n0 = nid[m0]; f0 = g_first[m0]; }
    if (m1 < NPAIR) { p1 = pid[m1]; n1 = nid[m1]; f1 = g_first[m1]; }
    float v0 = 0.0f, v1 = 0.0f;
    if (f0) v0 = __ldg(&probs[(size_t)n0 * NCLS + s_inst[p0]]);
    if (f1) v1 = __ldg(&probs[(size_t)n1 * NCLS + s_inst[p1]]);
    if (f0) atomicAdd(&s_scr[p0], v0);
    if (f1) atomicAdd(&s_scr[p1], v1);

    __syncthreads();
    if (tid < NPROP && s_scr[tid] != 0.0f)
        atomicAdd(&g_score_p[tid * PAD], s_scr[tid]);

    // ticket: last block performs finalize
    __shared__ int s_last;
    __threadfence();
    __syncthreads();
    if (tid == 0) s_last = (atomicAdd(&g_ticket, 1) == gridDim.x - 1) ? 1 : 0;
    __syncthreads();
    if (s_last && tid < NPROP) {
        int c = g_count_p[tid * PAD];
        int flag = (c > THRESH) ? 1 : 0;
        int cm = c > 1 ? c : 1;
        float sc = *(volatile float*)&g_score_p[tid * PAD];
        out_scores[tid]  = flag ? (sc / (float)cm) : 0.0f;
        out_classes[tid] = flag ? (float)s_inst[tid] : -1.0f;
    }
}

extern "C" void kernel_launch(void* const* d_in, const int* in_sizes, int n_in,
                              void* d_out, int out_size) {
    const float* logit = (const float*)d_in[0];
    const float* bias  = (const float*)d_in[1];
    // d_in[2] = coord: dead
    const int* pid = (const int*)d_in[3];
    const int* nid = (const int*)d_in[4];

    float* out = (float*)d_out;
    float* out_scores  = out + OFF_SCORES;
    float* out_masks   = out + OFF_MASKS;
    float* out_classes = out + OFF_CLASSES;
    float* out_bias    = out + OFF_BIAS;
    float* out_probs   = out + OFF_PROBS;

    static cudaStream_t sH = nullptr, sB = nullptr;
    static cudaEvent_t eRoot, eP, eH, eB;
    static void *a_bits = nullptr, *a_rep = nullptr, *a_cnt = nullptr, *a_scr = nullptr;
    if (!sH) {
        int loPri, hiPri;
        cudaDeviceGetStreamPriorityRange(&loPri, &hiPri);
        cudaStreamCreateWithPriority(&sH, cudaStreamNonBlocking, hiPri);
        cudaStreamCreateWithPriority(&sB, cudaStreamNonBlocking, loPri);
        cudaEventCreateWithFlags(&eRoot, cudaEventDisableTiming);
        cudaEventCreateWithFlags(&eP, cudaEventDisableTiming);
        cudaEventCreateWithFlags(&eH, cudaEventDisableTiming);
        cudaEventCreateWithFlags(&eB, cudaEventDisableTiming);
        cudaGetSymbolAddress(&a_bits, g_bits);
        cudaGetSymbolAddress(&a_rep,  g_rep_p);
        cudaGetSymbolAddress(&a_cnt,  g_count_p);
        cudaGetSymbolAddress(&a_scr,  g_score_p);
    }

    // fork from stream 0
    cudaEventRecord(eRoot, 0);
    cudaStreamWaitEvent(sH, eRoot, 0);
    cudaStreamWaitEvent(sB, eRoot, 0);

    // sH (critical, high priority): memsets -> pairs(Or+min+count+ticket) -> masks
    cudaMemsetAsync(a_bits, 0, WORDS * 4, sH);
    cudaMemsetAsync(a_cnt, 0, NPROP * PAD * 4, sH);
    cudaMemsetAsync(a_rep, 0x7F, NPROP * PAD * 4, sH);   // 0x7F7F7F7F > NPTS
    k_pairs<<<296, 1024, 0, sH>>>(pid, nid);
    cudaEventRecord(eP, sH);
    k_masks<<<(int)(WORDS / 256), 256, 0, sH>>>(out_masks);
    cudaEventRecord(eH, sH);

    // sB (low priority): memset scr -> softmax(+bias) -> (wait pairs) gather(+finalize)
    cudaMemsetAsync(a_scr, 0, NPROP * PAD * 4, sB);
    k_softmax<<<(NPTS + 255) / 256, 256, 0, sB>>>(logit, out_probs, bias, out_bias);
    cudaStreamWaitEvent(sB, eP, 0);
    k_gather<<<GGRID, GB, 0, sB>>>(pid, nid, out_probs, out_scores, out_classes);
    cudaEventRecord(eB, sB);

    // join into stream 0
    cudaStreamWaitEvent(0, eH, 0);
    cudaStreamWaitEvent(0, eB, 0);
}

// round 13
// speedup vs baseline: 1.1536x; 1.1536x over previous
#include <cuda_runtime.h>
#include <cstdint>

// Problem constants
#define NPTS 200000
#define NCLS 20
#define NPROP 256
#define NPAIR 400000
#define THRESH 100

// Derived
#define WPP (NPTS / 32)                 // 6250 words per proposal
#define WORDS ((size_t)NPROP * WPP)     // 1,600,000 words

// Output layout (float32, concatenated in return order)
#define OFF_SCORES  ((size_t)0)
#define OFF_MASKS   ((size_t)256)
#define OFF_CLASSES ((size_t)(256 + (size_t)NPROP * NPTS))
#define OFF_BIAS    (OFF_CLASSES + 256)
#define OFF_PROBS   (OFF_BIAS + (size_t)NPTS * 3)

#define PAD 32   // 128B stride between per-proposal counters

// Scratch (device globals: allocation-free)
__device__ unsigned int g_bits[WORDS];          // 6.4 MB dedupe bitmask
__device__ unsigned char g_first[NPAIR];        // per-pair first-setter verdict
__device__ int   g_rep_p[NPROP * PAD];
__device__ int   g_count_p[NPROP * PAD];
__device__ float g_score_p[NPROP * PAD];
__device__ int   g_segpred[NPTS];
__device__ int   g_ticket;                      // gather completion ticket

// Fast exp on FMA pipe (no MUFU). rel err ~2e-6.
__device__ __forceinline__ float fexp(float x) {
    const float MAGIC = 12582912.0f;           // 1.5 * 2^23
    float t = fmaf(x, 1.4426950408889634f, MAGIC);
    int   n = __float_as_int(t) - 0x4B400000;
    float f = fmaf(x, 1.4426950408889634f, -(t - MAGIC));
    float p = 1.3333558146e-3f;
    p = fmaf(p, f, 9.6181291076e-3f);
    p = fmaf(p, f, 5.5504108664e-2f);
    p = fmaf(p, f, 2.4022650696e-1f);
    p = fmaf(p, f, 6.9314718056e-1f);
    p = fmaf(p, f, 1.0f);
    return __int_as_float(__float_as_int(p) + (n << 23));
}

// --- sH: fused pair pass: atomicOr + verdict + smem segmin + smem count ---
__global__ void __launch_bounds__(1024, 2)
k_pairs(const int* __restrict__ pid, const int* __restrict__ nid) {
    __shared__ int s_min[NPROP];
    __shared__ int s_cnt[NPROP];
    int tid = threadIdx.x;
    if (tid < NPROP) { s_min[tid] = 0x7FFFFFFF; s_cnt[tid] = 0; }
    if (blockIdx.x == 0 && tid == 0) g_ticket = 0;
    __syncthreads();

    int stride = gridDim.x * blockDim.x;
    for (int m = blockIdx.x * blockDim.x + tid; m < NPAIR; m += stride) {
        int p = pid[m];
        int n = nid[m];
        atomicMin(&s_min[p], n);
        size_t bit = (size_t)p * NPTS + n;
        unsigned int msk = 1u << (bit & 31u);
        unsigned int old = atomicOr(&g_bits[bit >> 5], msk);
        unsigned char fst = (old & msk) ? 0 : 1;
        g_first[m] = fst;
        if (fst) atomicAdd(&s_cnt[p], 1);
    }
    __syncthreads();
    if (tid < NPROP) {
        if (s_min[tid] != 0x7FFFFFFF) atomicMin(&g_rep_p[tid * PAD], s_min[tid]);
        if (s_cnt[tid]) atomicAdd(&g_count_p[tid * PAD], s_cnt[tid]);
    }
}

// --- sH: mask expansion, warp-coalesced 512B streaming stores ---
__global__ void k_masks(float* __restrict__ out_masks) {
    int tid = threadIdx.x;
    int t = blockIdx.x * blockDim.x + tid;   // word index (exact grid)
    int lane = tid & 31;
    int p = t / WPP;
    unsigned int w = g_bits[t];
    if (g_count_p[p * PAD] <= THRESH) w = 0u;

    size_t warp_word0 = (size_t)(t - lane);
    float4* dst = (float4*)out_masks + warp_word0 * 8;   // 8 float4 per word
    int nib = (lane & 7) * 4;
#pragma unroll
    for (int i = 0; i < 8; i++) {
        unsigned int src = __shfl_sync(0xFFFFFFFFu, w, i * 4 + (lane >> 3));
        float4 f;
        f.x = (float)((src >> (nib + 0)) & 1u);
        f.y = (float)((src >> (nib + 1)) & 1u);
        f.z = (float)((src >> (nib + 2)) & 1u);
        f.w = (float)((src >> (nib + 3)) & 1u);
        __stcs(&dst[(size_t)i * 32 + lane], f);   // streaming: don't pollute L2
    }
}

// --- sB: softmax + argmax, float4 staging, fused bias passthrough ---
__global__ void k_softmax(const float* __restrict__ logit,
                          float* __restrict__ probs_out,
                          const float* __restrict__ bias,
                          float* __restrict__ bias_out) {
    __shared__ float4 s4[256 * 5];   // 20 KB
    int tid  = threadIdx.x;
    int base = blockIdx.x * 256;

    // fused bias copy: one float4 per thread across the grid (150000 total)
    {
        int bi = base + tid;
        if (bi < NPTS * 3 / 4) ((float4*)bias_out)[bi] = ((const float4*)bias)[bi];
    }

    int count = NPTS - base;
    if (count > 256) count = 256;
    int nf4 = count * 5;

    const float4* src = (const float4*)(logit + (size_t)base * NCLS);
#pragma unroll
    for (int i = tid; i < nf4; i += 256) s4[i] = src[i];
    __syncthreads();

    if (tid < count) {
        float v[NCLS];
#pragma unroll
        for (int i = 0; i < 5; i++) {
            float4 q = s4[tid * 5 + i];
            v[4 * i + 0] = q.x; v[4 * i + 1] = q.y;
            v[4 * i + 2] = q.z; v[4 * i + 3] = q.w;
        }
        float m = v[0]; int am = 0;
#pragma unroll
        for (int i = 1; i < NCLS; i++) if (v[i] > m) { m = v[i]; am = i; }
        float e[NCLS]; float sum = 0.0f;
#pragma unroll
        for (int i = 0; i < NCLS; i++) { e[i] = fexp(v[i] - m); sum += e[i]; }
        float inv = 1.0f / sum;
#pragma unroll
        for (int i = 0; i < 5; i++) {
            float4 q;
            q.x = e[4 * i + 0] * inv; q.y = e[4 * i + 1] * inv;
            q.z = e[4 * i + 2] * inv; q.w = e[4 * i + 3] * inv;
            s4[tid * 5 + i] = q;
        }
        g_segpred[base + tid] = am;
    }
    __syncthreads();

    float4* dst = (float4*)(probs_out + (size_t)base * NCLS);
#pragma unroll
    for (int i = tid; i < nf4; i += 256) dst[i] = s4[i];
}

// --- sB: score gather, 148 blocks, 3-deep batched loads, ticketed finalize ---
#define GB 1024
#define GGRIDN 148
__global__ void __launch_bounds__(GB, 1)
k_gather(const int* __restrict__ pid, const int* __restrict__ nid,
         const float* __restrict__ probs,
         float* __restrict__ out_scores, float* __restrict__ out_classes) {
    __shared__ int   s_inst[NPROP];
    __shared__ float s_scr[NPROP];
    int tid = threadIdx.x;
    if (tid < NPROP) {
        int r = g_rep_p[tid * PAD];
        if (r > NPTS - 1) r = NPTS - 1;
        s_inst[tid] = g_segpred[r];
        s_scr[tid] = 0.0f;
    }
    __syncthreads();

    const int S = GGRIDN * GB;                 // 151552
    int m0 = blockIdx.x * GB + tid;
    int m1 = m0 + S;
    int m2 = m1 + S;

    // batch all pair loads before any use (3-deep MLP)
    int p0 = 0, n0 = 0, p1 = 0, n1 = 0, p2 = 0, n2 = 0;
    unsigned char f0 = 0, f1 = 0, f2 = 0;
    if (m0 < NPAIR) { p0 = pid[m0]; n0 = nid[m0]; f0 = g_first[m0]; }
    if (m1 < NPAIR) { p1 = pid[m1]; n1 = nid[m1]; f1 = g_first[m1]; }
    if (m2 < NPAIR) { p2 = pid[m2]; n2 = nid[m2]; f2 = g_first[m2]; }

    float v0 = 0.0f, v1 = 0.0f, v2 = 0.0f;
    if (f0) v0 = __ldg(&probs[(size_t)n0 * NCLS + s_inst[p0]]);
    if (f1) v1 = __ldg(&probs[(size_t)n1 * NCLS + s_inst[p1]]);
    if (f2) v2 = __ldg(&probs[(size_t)n2 * NCLS + s_inst[p2]]);
    if (f0) atomicAdd(&s_scr[p0], v0);
    if (f1) atomicAdd(&s_scr[p1], v1);
    if (f2) atomicAdd(&s_scr[p2], v2);

    __syncthreads();
    if (tid < NPROP && s_scr[tid] != 0.0f)
        atomicAdd(&g_score_p[tid * PAD], s_scr[tid]);

    // ticket: last block performs finalize
    __shared__ int s_last;
    __threadfence();
    __syncthreads();
    if (tid == 0) s_last = (atomicAdd(&g_ticket, 1) == gridDim.x - 1) ? 1 : 0;
    __syncthreads();
    if (s_last && tid < NPROP) {
        int c = g_count_p[tid * PAD];
        int flag = (c > THRESH) ? 1 : 0;
        int cm = c > 1 ? c : 1;
        float sc = *(volatile float*)&g_score_p[tid * PAD];
        out_scores[tid]  = flag ? (sc / (float)cm) : 0.0f;
        out_classes[tid] = flag ? (float)s_inst[tid] : -1.0f;
    }
}

extern "C" void kernel_launch(void* const* d_in, const int* in_sizes, int n_in,
                              void* d_out, int out_size) {
    const float* logit = (const float*)d_in[0];
    const float* bias  = (const float*)d_in[1];
    // d_in[2] = coord: dead
    const int* pid = (const int*)d_in[3];
    const int* nid = (const int*)d_in[4];

    float* out = (float*)d_out;
    float* out_scores  = out + OFF_SCORES;
    float* out_masks   = out + OFF_MASKS;
    float* out_classes = out + OFF_CLASSES;
    float* out_bias    = out + OFF_BIAS;
    float* out_probs   = out + OFF_PROBS;

    static cudaStream_t sH = nullptr, sB = nullptr;
    static cudaEvent_t eRoot, eP, eH, eB;
    static void *a_bits = nullptr, *a_rep = nullptr, *a_cnt = nullptr, *a_scr = nullptr;
    if (!sH) {
        int loPri, hiPri;
        cudaDeviceGetStreamPriorityRange(&loPri, &hiPri);
        cudaStreamCreateWithPriority(&sH, cudaStreamNonBlocking, hiPri);
        cudaStreamCreateWithPriority(&sB, cudaStreamNonBlocking, loPri);
        cudaEventCreateWithFlags(&eRoot, cudaEventDisableTiming);
        cudaEventCreateWithFlags(&eP, cudaEventDisableTiming);
        cudaEventCreateWithFlags(&eH, cudaEventDisableTiming);
        cudaEventCreateWithFlags(&eB, cudaEventDisableTiming);
        cudaGetSymbolAddress(&a_bits, g_bits);
        cudaGetSymbolAddress(&a_rep,  g_rep_p);
        cudaGetSymbolAddress(&a_cnt,  g_count_p);
        cudaGetSymbolAddress(&a_scr,  g_score_p);
    }

    // fork from stream 0
    cudaEventRecord(eRoot, 0);
    cudaStreamWaitEvent(sH, eRoot, 0);
    cudaStreamWaitEvent(sB, eRoot, 0);

    // sH (critical, high priority): memsets -> pairs(Or+min+count+ticket) -> masks
    cudaMemsetAsync(a_bits, 0, WORDS * 4, sH);
    cudaMemsetAsync(a_cnt, 0, NPROP * PAD * 4, sH);
    cudaMemsetAsync(a_rep, 0x7F, NPROP * PAD * 4, sH);   // 0x7F7F7F7F > NPTS
    k_pairs<<<296, 1024, 0, sH>>>(pid, nid);
    cudaEventRecord(eP, sH);
    k_masks<<<(int)(WORDS / 256), 256, 0, sH>>>(out_masks);
    cudaEventRecord(eH, sH);

    // sB (low priority): memset scr -> softmax(+bias) -> (wait pairs) gather(+finalize)
    cudaMemsetAsync(a_scr, 0, NPROP * PAD * 4, sB);
    k_softmax<<<(NPTS + 255) / 256, 256, 0, sB>>>(logit, out_probs, bias, out_bias);
    cudaStreamWaitEvent(sB, eP, 0);
    k_gather<<<GGRIDN, GB, 0, sB>>>(pid, nid, out_probs, out_scores, out_classes);
    cudaEventRecord(eB, sB);

    // join into stream 0
    cudaStreamWaitEvent(0, eH, 0);
    cudaStreamWaitEvent(0, eB, 0);
}

// round 14
// speedup vs baseline: 1.1966x; 1.0373x over previous
#include <cuda_runtime.h>
#include <cstdint>

// Problem constants
#define NPTS 200000
#define NCLS 20
#define NPROP 256
#define NPAIR 400000
#define THRESH 100

// Derived
#define WPP (NPTS / 32)                 // 6250 words per proposal
#define WORDS ((size_t)NPROP * WPP)     // 1,600,000 words

// Output layout (float32, concatenated in return order)
#define OFF_SCORES  ((size_t)0)
#define OFF_MASKS   ((size_t)256)
#define OFF_CLASSES ((size_t)(256 + (size_t)NPROP * NPTS))
#define OFF_BIAS    (OFF_CLASSES + 256)
#define OFF_PROBS   (OFF_BIAS + (size_t)NPTS * 3)

#define PAD 32   // 128B stride between per-proposal counters

// One contiguous zero-region: [bits | counts | scores] -> single memset(0)
#define ZWORDS (WORDS + 2 * NPROP * PAD)
__device__ unsigned int g_zero[ZWORDS];
#define G_BITS(i)  (g_zero[i])
#define G_CNT_PTR  ((int*)(g_zero + WORDS))
#define G_SCR_PTR  ((float*)(g_zero + WORDS + NPROP * PAD))

__device__ unsigned char g_first[NPAIR];        // per-pair first-setter verdict
__device__ int   g_rep_p[NPROP * PAD];          // memset 0x7F separately
__device__ int   g_segpred[NPTS];
__device__ int   g_ticket;                      // gather completion ticket

// Fast exp on FMA pipe (no MUFU). rel err ~2e-6.
__device__ __forceinline__ float fexp(float x) {
    const float MAGIC = 12582912.0f;           // 1.5 * 2^23
    float t = fmaf(x, 1.4426950408889634f, MAGIC);
    int   n = __float_as_int(t) - 0x4B400000;
    float f = fmaf(x, 1.4426950408889634f, -(t - MAGIC));
    float p = 1.3333558146e-3f;
    p = fmaf(p, f, 9.6181291076e-3f);
    p = fmaf(p, f, 5.5504108664e-2f);
    p = fmaf(p, f, 2.4022650696e-1f);
    p = fmaf(p, f, 6.9314718056e-1f);
    p = fmaf(p, f, 1.0f);
    return __int_as_float(__float_as_int(p) + (n << 23));
}

// --- sH: fused pair pass, 3-deep batched atomics: atomicOr + verdict + segmin + count ---
#define PB 1024
#define PGRIDN 148
__global__ void __launch_bounds__(PB, 1)
k_pairs(const int* __restrict__ pid, const int* __restrict__ nid) {
    __shared__ int s_min[NPROP];
    __shared__ int s_cnt[NPROP];
    int tid = threadIdx.x;
    if (tid < NPROP) { s_min[tid] = 0x7FFFFFFF; s_cnt[tid] = 0; }
    if (blockIdx.x == 0 && tid == 0) g_ticket = 0;
    __syncthreads();

    const int S = PGRIDN * PB;                 // 151552
    int m0 = blockIdx.x * PB + tid;
    int m1 = m0 + S;
    int m2 = m1 + S;

    // batch pair loads (independent, all in flight)
    int p0 = 0, n0 = 0, p1 = 0, n1 = 0, p2 = 0, n2 = 0;
    bool a0 = m0 < NPAIR, a1 = m1 < NPAIR, a2 = m2 < NPAIR;
    if (a0) { p0 = pid[m0]; n0 = nid[m0]; }
    if (a1) { p1 = pid[m1]; n1 = nid[m1]; }
    if (a2) { p2 = pid[m2]; n2 = nid[m2]; }

    // 3 independent global atomicOr round-trips in flight
    unsigned int w0 = 0, w1 = 0, w2 = 0, k0 = 0, k1 = 0, k2 = 0;
    if (a0) { size_t b = (size_t)p0 * NPTS + n0; k0 = 1u << (b & 31u); w0 = atomicOr(&G_BITS(b >> 5), k0); }
    if (a1) { size_t b = (size_t)p1 * NPTS + n1; k1 = 1u << (b & 31u); w1 = atomicOr(&G_BITS(b >> 5), k1); }
    if (a2) { size_t b = (size_t)p2 * NPTS + n2; k2 = 1u << (b & 31u); w2 = atomicOr(&G_BITS(b >> 5), k2); }

    unsigned char f0 = (a0 && !(w0 & k0)) ? 1 : 0;
    unsigned char f1 = (a1 && !(w1 & k1)) ? 1 : 0;
    unsigned char f2 = (a2 && !(w2 & k2)) ? 1 : 0;
    if (a0) g_first[m0] = f0;
    if (a1) g_first[m1] = f1;
    if (a2) g_first[m2] = f2;

    if (a0) atomicMin(&s_min[p0], n0);
    if (a1) atomicMin(&s_min[p1], n1);
    if (a2) atomicMin(&s_min[p2], n2);
    if (f0) atomicAdd(&s_cnt[p0], 1);
    if (f1) atomicAdd(&s_cnt[p1], 1);
    if (f2) atomicAdd(&s_cnt[p2], 1);

    __syncthreads();
    if (tid < NPROP) {
        if (s_min[tid] != 0x7FFFFFFF) atomicMin(&g_rep_p[tid * PAD], s_min[tid]);
        if (s_cnt[tid]) atomicAdd(&G_CNT_PTR[tid * PAD], s_cnt[tid]);
    }
}

// --- sH: mask expansion, warp-coalesced 512B streaming stores ---
__global__ void k_masks(float* __restrict__ out_masks) {
    int tid = threadIdx.x;
    int t = blockIdx.x * blockDim.x + tid;   // word index (exact grid)
    int lane = tid & 31;
    int p = t / WPP;
    unsigned int w = G_BITS(t);
    if (G_CNT_PTR[p * PAD] <= THRESH) w = 0u;

    size_t warp_word0 = (size_t)(t - lane);
    float4* dst = (float4*)out_masks + warp_word0 * 8;   // 8 float4 per word
    int nib = (lane & 7) * 4;
#pragma unroll
    for (int i = 0; i < 8; i++) {
        unsigned int src = __shfl_sync(0xFFFFFFFFu, w, i * 4 + (lane >> 3));
        float4 f;
        f.x = (float)((src >> (nib + 0)) & 1u);
        f.y = (float)((src >> (nib + 1)) & 1u);
        f.z = (float)((src >> (nib + 2)) & 1u);
        f.w = (float)((src >> (nib + 3)) & 1u);
        __stcs(&dst[(size_t)i * 32 + lane], f);   // streaming: don't pollute L2
    }
}

// --- sB: softmax + argmax, float4 staging, fused bias passthrough ---
__global__ void k_softmax(const float* __restrict__ logit,
                          float* __restrict__ probs_out,
                          const float* __restrict__ bias,
                          float* __restrict__ bias_out) {
    __shared__ float4 s4[256 * 5];   // 20 KB
    int tid  = threadIdx.x;
    int base = blockIdx.x * 256;

    // fused bias copy: one float4 per thread across the grid (150000 total)
    {
        int bi = base + tid;
        if (bi < NPTS * 3 / 4) ((float4*)bias_out)[bi] = ((const float4*)bias)[bi];
    }

    int count = NPTS - base;
    if (count > 256) count = 256;
    int nf4 = count * 5;

    const float4* src = (const float4*)(logit + (size_t)base * NCLS);
#pragma unroll
    for (int i = tid; i < nf4; i += 256) s4[i] = src[i];
    __syncthreads();

    if (tid < count) {
        float v[NCLS];
#pragma unroll
        for (int i = 0; i < 5; i++) {
            float4 q = s4[tid * 5 + i];
            v[4 * i + 0] = q.x; v[4 * i + 1] = q.y;
            v[4 * i + 2] = q.z; v[4 * i + 3] = q.w;
        }
        float m = v[0]; int am = 0;
#pragma unroll
        for (int i = 1; i < NCLS; i++) if (v[i] > m) { m = v[i]; am = i; }
        float e[NCLS]; float sum = 0.0f;
#pragma unroll
        for (int i = 0; i < NCLS; i++) { e[i] = fexp(v[i] - m); sum += e[i]; }
        float inv = 1.0f / sum;
#pragma unroll
        for (int i = 0; i < 5; i++) {
            float4 q;
            q.x = e[4 * i + 0] * inv; q.y = e[4 * i + 1] * inv;
            q.z = e[4 * i + 2] * inv; q.w = e[4 * i + 3] * inv;
            s4[tid * 5 + i] = q;
        }
        g_segpred[base + tid] = am;
    }
    __syncthreads();

    float4* dst = (float4*)(probs_out + (size_t)base * NCLS);
#pragma unroll
    for (int i = tid; i < nf4; i += 256) dst[i] = s4[i];
}

// --- sB: score gather, 148 blocks, 3-deep batched loads, ticketed finalize ---
#define GB 1024
#define GGRIDN 148
__global__ void __launch_bounds__(GB, 1)
k_gather(const int* __restrict__ pid, const int* __restrict__ nid,
         const float* __restrict__ probs,
         float* __restrict__ out_scores, float* __restrict__ out_classes) {
    __shared__ int   s_inst[NPROP];
    __shared__ float s_scr[NPROP];
    int tid = threadIdx.x;
    if (tid < NPROP) {
        int r = g_rep_p[tid * PAD];
        if (r > NPTS - 1) r = NPTS - 1;
        s_inst[tid] = g_segpred[r];
        s_scr[tid] = 0.0f;
    }
    __syncthreads();

    const int S = GGRIDN * GB;                 // 151552
    int m0 = blockIdx.x * GB + tid;
    int m1 = m0 + S;
    int m2 = m1 + S;

    int p0 = 0, n0 = 0, p1 = 0, n1 = 0, p2 = 0, n2 = 0;
    unsigned char f0 = 0, f1 = 0, f2 = 0;
    if (m0 < NPAIR) { p0 = pid[m0]; n0 = nid[m0]; f0 = g_first[m0]; }
    if (m1 < NPAIR) { p1 = pid[m1]; n1 = nid[m1]; f1 = g_first[m1]; }
    if (m2 < NPAIR) { p2 = pid[m2]; n2 = nid[m2]; f2 = g_first[m2]; }

    float v0 = 0.0f, v1 = 0.0f, v2 = 0.0f;
    if (f0) v0 = __ldg(&probs[(size_t)n0 * NCLS + s_inst[p0]]);
    if (f1) v1 = __ldg(&probs[(size_t)n1 * NCLS + s_inst[p1]]);
    if (f2) v2 = __ldg(&probs[(size_t)n2 * NCLS + s_inst[p2]]);
    if (f0) atomicAdd(&s_scr[p0], v0);
    if (f1) atomicAdd(&s_scr[p1], v1);
    if (f2) atomicAdd(&s_scr[p2], v2);

    __syncthreads();
    if (tid < NPROP && s_scr[tid] != 0.0f)
        atomicAdd(&G_SCR_PTR[tid * PAD], s_scr[tid]);

    // ticket: last block performs finalize
    __shared__ int s_last;
    __threadfence();
    __syncthreads();
    if (tid == 0) s_last = (atomicAdd(&g_ticket, 1) == gridDim.x - 1) ? 1 : 0;
    __syncthreads();
    if (s_last && tid < NPROP) {
        int c = G_CNT_PTR[tid * PAD];
        int flag = (c > THRESH) ? 1 : 0;
        int cm = c > 1 ? c : 1;
        float sc = *(volatile float*)&G_SCR_PTR[tid * PAD];
        out_scores[tid]  = flag ? (sc / (float)cm) : 0.0f;
        out_classes[tid] = flag ? (float)s_inst[tid] : -1.0f;
    }
}

extern "C" void kernel_launch(void* const* d_in, const int* in_sizes, int n_in,
                              void* d_out, int out_size) {
    const float* logit = (const float*)d_in[0];
    const float* bias  = (const float*)d_in[1];
    // d_in[2] = coord: dead
    const int* pid = (const int*)d_in[3];
    const int* nid = (const int*)d_in[4];

    float* out = (float*)d_out;
    float* out_scores  = out + OFF_SCORES;
    float* out_masks   = out + OFF_MASKS;
    float* out_classes = out + OFF_CLASSES;
    float* out_bias    = out + OFF_BIAS;
    float* out_probs   = out + OFF_PROBS;

    static cudaStream_t sH = nullptr, sB = nullptr;
    static cudaEvent_t eRoot, eP, eH, eB;
    static void *a_zero = nullptr, *a_rep = nullptr;
    if (!sH) {
        int loPri, hiPri;
        cudaDeviceGetStreamPriorityRange(&loPri, &hiPri);
        cudaStreamCreateWithPriority(&sH, cudaStreamNonBlocking, hiPri);
        cudaStreamCreateWithPriority(&sB, cudaStreamNonBlocking, loPri);
        cudaEventCreateWithFlags(&eRoot, cudaEventDisableTiming);
        cudaEventCreateWithFlags(&eP, cudaEventDisableTiming);
        cudaEventCreateWithFlags(&eH, cudaEventDisableTiming);
        cudaEventCreateWithFlags(&eB, cudaEventDisableTiming);
        cudaGetSymbolAddress(&a_zero, g_zero);
        cudaGetSymbolAddress(&a_rep,  g_rep_p);
    }

    // fork from stream 0
    cudaEventRecord(eRoot, 0);
    cudaStreamWaitEvent(sH, eRoot, 0);
    cudaStreamWaitEvent(sB, eRoot, 0);

    // sH (critical, high priority): 2 memsets -> pairs -> masks
    cudaMemsetAsync(a_zero, 0, ZWORDS * 4, sH);          // bits + counts + scores
    cudaMemsetAsync(a_rep, 0x7F, NPROP * PAD * 4, sH);   // 0x7F7F7F7F > NPTS
    k_pairs<<<PGRIDN, PB, 0, sH>>>(pid, nid);
    cudaEventRecord(eP, sH);
    k_masks<<<(int)(WORDS / 256), 256, 0, sH>>>(out_masks);
    cudaEventRecord(eH, sH);

    // sB (low priority): softmax(+bias) -> (wait pairs) gather(+finalize)
    k_softmax<<<(NPTS + 255) / 256, 256, 0, sB>>>(logit, out_probs, bias, out_bias);
    cudaStreamWaitEvent(sB, eP, 0);
    k_gather<<<GGRIDN, GB, 0, sB>>>(pid, nid, out_probs, out_scores, out_classes);
    cudaEventRecord(eB, sB);

    // join into stream 0
    cudaStreamWaitEvent(0, eH, 0);
    cudaStreamWaitEvent(0, eB, 0);
}